// round 13
// baseline (speedup 1.0000x reference)
#include <cuda_runtime.h>
#include <cstdint>

#define N_NODES 100000
#define N_EDGES 1600000
#define F_INF   50
#define F_PAD   52            // padded row stride for float4 alignment
#define HID     64
#define NGRAPH  512
#define NCLS    10
#define BONDD   10

#define MTILE   128           // nodes per dense block
#define KC      16            // k-chunk staged in smem (double-buffered)
#define SA_STR  132           // sA row stride (floats), mult of 4 for LDS.128
#define SW_STR  68            // sW row stride (floats), mult of 4

// ---------------- scratch (static __device__ — no allocations) ----------------
__device__ __align__(16) float d_ew[N_EDGES];
__device__ __align__(16) float d_x52[N_NODES * F_PAD];
__device__ __align__(16) float d_agg1[N_NODES * F_PAD];
__device__ __align__(16) float d_h1[N_NODES * HID];       // stores relu(h1)
__device__ __align__(16) float d_agg2[N_NODES * HID];
__device__ __align__(16) float d_psum1[NGRAPH * HID];
__device__ __align__(16) float d_pmax1[NGRAPH * HID];
__device__ __align__(16) float d_psum2[NGRAPH * HID];
__device__ __align__(16) float d_pmax2[NGRAPH * HID];

// ---------------- helpers ----------------
__device__ __forceinline__ void redAdd4(float* a, float x, float y, float z, float w) {
    asm volatile("red.global.add.v4.f32 [%0], {%1,%2,%3,%4};"
                 :: "l"(a), "f"(x), "f"(y), "f"(z), "f"(w) : "memory");
}
__device__ __forceinline__ void atomicMaxF(float* addr, float v) {
    if (v >= 0.0f) atomicMax((int*)addr, __float_as_int(v));
    else           atomicMin((unsigned int*)addr, __float_as_uint(v));
}

// ---------------- small kernels ----------------
__global__ void k_padx(const float* __restrict__ x) {
    int idx = blockIdx.x * blockDim.x + threadIdx.x;
    if (idx >= N_NODES * F_PAD) return;
    int n = idx / F_PAD;
    int f = idx - n * F_PAD;
    d_x52[idx] = (f < F_INF) ? x[n * F_INF + f] : 0.0f;
}

__global__ void k_ew(const float* __restrict__ edge_a,
                     const float* __restrict__ bond_w,
                     const float* __restrict__ bond_b) {
    int e = blockIdx.x * blockDim.x + threadIdx.x;
    if (e >= N_EDGES) return;
    const float2* a2 = (const float2*)(edge_a + e * BONDD);
    float acc = bond_b[0];
#pragma unroll
    for (int i = 0; i < 5; i++) {
        float2 v = a2[i];
        acc += v.x * bond_w[2 * i] + v.y * bond_w[2 * i + 1];
    }
    d_ew[e] = acc;
}

// Scatter kernels: 16 lanes per edge (lane-aligned). Leader lane loads
// src/dst/ew once; __shfl_sync broadcasts. Grid is exact (E*16 % 256 == 0).
// conv1: q<13 lanes move 13 float4 (52 padded floats).
__global__ __launch_bounds__(256) void k_scatter1(const int* __restrict__ ei) {
    int t = blockIdx.x * 256 + threadIdx.x;
    int e = t >> 4;
    int q = t & 15;
    int lane = threadIdx.x & 31;
    int leader = lane & ~15;
    int src = 0, dst = 0; float w = 0.0f;
    if ((lane & 15) == 0) {
        src = ei[e];
        dst = ei[N_EDGES + e];
        w = d_ew[e];
    }
    src = __shfl_sync(0xffffffffu, src, leader);
    dst = __shfl_sync(0xffffffffu, dst, leader);
    w   = __shfl_sync(0xffffffffu, w,   leader);
    if (q < 13) {
        float4 v = ((const float4*)(d_x52 + src * F_PAD))[q];
        redAdd4(d_agg1 + dst * F_PAD + q * 4, v.x * w, v.y * w, v.z * w, v.w * w);
    }
}

// conv2: all 16 lanes move 16 float4 (h1 already relu'd).
__global__ __launch_bounds__(256) void k_scatter2(const int* __restrict__ ei) {
    int t = blockIdx.x * 256 + threadIdx.x;
    int e = t >> 4;
    int q = t & 15;
    int lane = threadIdx.x & 31;
    int leader = lane & ~15;
    int src = 0, dst = 0; float w = 0.0f;
    if ((lane & 15) == 0) {
        src = ei[e];
        dst = ei[N_EDGES + e];
        w = d_ew[e];
    }
    src = __shfl_sync(0xffffffffu, src, leader);
    dst = __shfl_sync(0xffffffffu, dst, leader);
    w   = __shfl_sync(0xffffffffu, w,   leader);
    float4 v = ((const float4*)(d_h1 + src * HID))[q];
    redAdd4(d_agg2 + dst * HID + q * 4, v.x * w, v.y * w, v.z * w, v.w * w);
}

// Dense GEMM + fused pooling: h = [agg|xin] @ [rel|root]^T + b.
// 128 nodes x 64 cols per block, 256 threads, 8x4 reg tile, LDS.128 mainloop.
// A staged through smem in KC=16 chunks, double-buffered via register staging;
// W fully resident (zero-padded to KP). 4 CTAs/SM.
template <int F, int ASTRIDE, int XSTRIDE, bool STORE_H, bool RELU_STORE>
__global__ __launch_bounds__(256, 4) void k_dense_pool(
    const float* __restrict__ aggp, const float* __restrict__ xin,
    const float* __restrict__ rel_w, const float* __restrict__ rel_b,
    const float* __restrict__ root_w, const int* __restrict__ batch,
    float* __restrict__ h_out, float* __restrict__ pmax, float* __restrict__ psum) {
    constexpr int K  = 2 * F;
    constexpr int NC = (K + KC - 1) / KC;
    constexpr int KP = NC * KC;
    extern __shared__ float smem[];
    float* sW = smem;                  // [KP][SW_STR]
    float* sA = smem + KP * SW_STR;    // [2][KC][SA_STR]

    int tid = threadIdx.x;
    int node0 = blockIdx.x * MTILE;

    for (int idx = tid; idx < 64 * KP; idx += 256) {
        int j = idx / KP;
        int kg = idx - j * KP;
        float w = 0.0f;
        if (kg < F)      w = rel_w[j * F + kg];
        else if (kg < K) w = root_w[j * F + (kg - F)];
        sW[kg * SW_STR + j] = w;
    }

    auto ldA = [&](int c, float r[8]) {
#pragma unroll
        for (int i = 0; i < 8; i++) {
            int idx = tid + i * 256;
            int m  = idx >> 4;
            int kk = idx & 15;
            int kg = c * KC + kk;
            int node = node0 + m;
            float v = 0.0f;
            if (node < N_NODES) {
                if (kg < F)      v = aggp[node * ASTRIDE + kg];
                else if (kg < K) v = xin[node * XSTRIDE + (kg - F)];
            }
            r[i] = v;
        }
    };
    auto stA = [&](int c, const float r[8]) {
        float* buf = sA + (c & 1) * KC * SA_STR;
#pragma unroll
        for (int i = 0; i < 8; i++) {
            int idx = tid + i * 256;
            int m  = idx >> 4;
            int kk = idx & 15;
            buf[kk * SA_STR + m] = r[i];
        }
    };

    { float r[8]; ldA(0, r); stA(0, r); }
    __syncthreads();

    int tx = tid & 15;
    int ty = tid >> 4;
    float acc[8][4] = {};

    for (int c = 0; c < NC; c++) {
        float r[8];
        if (c + 1 < NC) ldA(c + 1, r);
        const float* buf = sA + (c & 1) * KC * SA_STR;
        const float4* pA0 = (const float4*)(buf + ty * 8);
        const float4* pA1 = (const float4*)(buf + ty * 8 + 4);
        const float4* pW  = (const float4*)(sW + c * KC * SW_STR + tx * 4);
#pragma unroll
        for (int kk = 0; kk < KC; kk++) {
            float4 a0 = pA0[kk * (SA_STR / 4)];
            float4 a1 = pA1[kk * (SA_STR / 4)];
            float4 w  = pW [kk * (SW_STR / 4)];
            acc[0][0] += a0.x * w.x; acc[0][1] += a0.x * w.y; acc[0][2] += a0.x * w.z; acc[0][3] += a0.x * w.w;
            acc[1][0] += a0.y * w.x; acc[1][1] += a0.y * w.y; acc[1][2] += a0.y * w.z; acc[1][3] += a0.y * w.w;
            acc[2][0] += a0.z * w.x; acc[2][1] += a0.z * w.y; acc[2][2] += a0.z * w.z; acc[2][3] += a0.z * w.w;
            acc[3][0] += a0.w * w.x; acc[3][1] += a0.w * w.y; acc[3][2] += a0.w * w.z; acc[3][3] += a0.w * w.w;
            acc[4][0] += a1.x * w.x; acc[4][1] += a1.x * w.y; acc[4][2] += a1.x * w.z; acc[4][3] += a1.x * w.w;
            acc[5][0] += a1.y * w.x; acc[5][1] += a1.y * w.y; acc[5][2] += a1.y * w.z; acc[5][3] += a1.y * w.w;
            acc[6][0] += a1.z * w.x; acc[6][1] += a1.z * w.y; acc[6][2] += a1.z * w.z; acc[6][3] += a1.z * w.w;
            acc[7][0] += a1.w * w.x; acc[7][1] += a1.w * w.y; acc[7][2] += a1.w * w.z; acc[7][3] += a1.w * w.w;
        }
        if (c + 1 < NC) stA(c + 1, r);
        __syncthreads();
    }

    float b0 = rel_b[tx * 4 + 0], b1 = rel_b[tx * 4 + 1];
    float b2 = rel_b[tx * 4 + 2], b3 = rel_b[tx * 4 + 3];

    float* sT = smem;                        // [MTILE][65]
    int*   sB = (int*)(smem + MTILE * 65);   // [MTILE]
    for (int m = tid; m < MTILE; m += 256)
        sB[m] = (node0 + m < N_NODES) ? batch[node0 + m] : -1;

#pragma unroll
    for (int i = 0; i < 8; i++) {
        float* row = sT + (ty * 8 + i) * 65 + tx * 4;
        row[0] = acc[i][0] + b0;
        row[1] = acc[i][1] + b1;
        row[2] = acc[i][2] + b2;
        row[3] = acc[i][3] + b3;
    }
    __syncthreads();

    if (STORE_H) {
        for (int idx = tid; idx < MTILE * 16; idx += 256) {
            int m = idx >> 4;
            int cg = idx & 15;
            int node = node0 + m;
            if (node < N_NODES) {
                float* row = sT + m * 65 + cg * 4;
                float4 o = make_float4(row[0], row[1], row[2], row[3]);
                if (RELU_STORE) {
                    o.x = fmaxf(o.x, 0.0f); o.y = fmaxf(o.y, 0.0f);
                    o.z = fmaxf(o.z, 0.0f); o.w = fmaxf(o.w, 0.0f);
                }
                *(float4*)(h_out + node * HID + cg * 4) = o;
            }
        }
    }

    {
        int col = tid & 63;
        int sub = tid >> 6;
        int base = sub * 32;
        int g_cur = sB[base];
        float sm = 0.0f;
        float mx = __int_as_float(0xff800000);
#pragma unroll 4
        for (int k = 0; k < 32; k++) {
            int g = sB[base + k];
            if (g < 0) break;
            if (g != g_cur) {
                atomicAdd(&psum[g_cur * HID + col], sm);
                atomicMaxF(&pmax[g_cur * HID + col], mx);
                sm = 0.0f; mx = __int_as_float(0xff800000);
                g_cur = g;
            }
            float vv = sT[(base + k) * 65 + col];
            sm += vv;
            mx = fmaxf(mx, vv);
        }
        if (g_cur >= 0) {
            atomicAdd(&psum[g_cur * HID + col], sm);
            atomicMaxF(&pmax[g_cur * HID + col], mx);
        }
    }
}

// head: counts via binary search on sorted batch; 2-layer MLP per graph.
__global__ __launch_bounds__(64) void k_head(
    const int* __restrict__ batch,
    const float* __restrict__ l1w, const float* __restrict__ l1b,
    const float* __restrict__ l2w, const float* __restrict__ l2b,
    float* __restrict__ out) {
    __shared__ float sg[2 * HID];
    __shared__ float sh[HID];
    __shared__ float scnt;
    int g = blockIdx.x;
    int j = threadIdx.x;
    if (j == 0) {
        int lo = 0, hi = N_NODES;
        while (lo < hi) { int m = (lo + hi) >> 1; if (batch[m] < g) lo = m + 1; else hi = m; }
        int lo2 = lo, hi2 = N_NODES;
        while (lo2 < hi2) { int m = (lo2 + hi2) >> 1; if (batch[m] < g + 1) lo2 = m + 1; else hi2 = m; }
        scnt = (float)(lo2 - lo);
    }
    __syncthreads();
    float inv = 1.0f / fmaxf(scnt, 1.0f);
    sg[j]       = d_pmax1[g * HID + j] + d_pmax2[g * HID + j];
    sg[HID + j] = (d_psum1[g * HID + j] + d_psum2[g * HID + j]) * inv;
    __syncthreads();
    float acc = l1b[j];
#pragma unroll 8
    for (int k = 0; k < 2 * HID; k++) acc += l1w[j * 2 * HID + k] * sg[k];
    sh[j] = fmaxf(acc, 0.0f);
    __syncthreads();
    if (j < NCLS) {
        float o = l2b[j];
#pragma unroll 8
        for (int k = 0; k < HID; k++) o += l2w[j * HID + k] * sh[k];
        out[g * NCLS + j] = o;
    }
}

// ---------------- launch ----------------
extern "C" void kernel_launch(void* const* d_in, const int* in_sizes, int n_in,
                              void* d_out, int out_size) {
    (void)in_sizes; (void)n_in; (void)out_size;
    const float* x      = (const float*)d_in[0];
    const float* edge_a = (const float*)d_in[1];
    const float* bond_w = (const float*)d_in[2];
    const float* bond_b = (const float*)d_in[3];
    const float* c1rw   = (const float*)d_in[4];
    const float* c1rb   = (const float*)d_in[5];
    const float* c1ow   = (const float*)d_in[6];
    const float* c2rw   = (const float*)d_in[7];
    const float* c2rb   = (const float*)d_in[8];
    const float* c2ow   = (const float*)d_in[9];
    const float* l1w    = (const float*)d_in[10];
    const float* l1b    = (const float*)d_in[11];
    const float* l2w    = (const float*)d_in[12];
    const float* l2b    = (const float*)d_in[13];
    const int*   ei     = (const int*)d_in[14];
    const int*   batch  = (const int*)d_in[15];
    float* out = (float*)d_out;

    float *p_agg1, *p_agg2, *p_h1, *p_ps1, *p_pm1, *p_ps2, *p_pm2;
    cudaGetSymbolAddress((void**)&p_agg1, d_agg1);
    cudaGetSymbolAddress((void**)&p_agg2, d_agg2);
    cudaGetSymbolAddress((void**)&p_h1,   d_h1);
    cudaGetSymbolAddress((void**)&p_ps1,  d_psum1);
    cudaGetSymbolAddress((void**)&p_pm1,  d_pmax1);
    cudaGetSymbolAddress((void**)&p_ps2,  d_psum2);
    cudaGetSymbolAddress((void**)&p_pm2,  d_pmax2);

    const int KP1 = ((100 + KC - 1) / KC) * KC;  // 112
    const int KP2 = ((128 + KC - 1) / KC) * KC;  // 128
    const int SMEM1 = (KP1 * SW_STR + 2 * KC * SA_STR) * (int)sizeof(float);  // ~47.4 KB
    const int SMEM2 = (KP2 * SW_STR + 2 * KC * SA_STR) * (int)sizeof(float);  // ~51.7 KB
    cudaFuncSetAttribute((const void*)k_dense_pool<50, F_PAD, F_INF, true, true>,
                         cudaFuncAttributeMaxDynamicSharedMemorySize, SMEM1);
    cudaFuncSetAttribute((const void*)k_dense_pool<64, HID, HID, false, false>,
                         cudaFuncAttributeMaxDynamicSharedMemorySize, SMEM2);

    cudaMemsetAsync(p_agg1, 0, N_NODES * F_PAD * sizeof(float));
    cudaMemsetAsync(p_agg2, 0, N_NODES * HID * sizeof(float));
    cudaMemsetAsync(p_ps1, 0, NGRAPH * HID * sizeof(float));
    cudaMemsetAsync(p_ps2, 0, NGRAPH * HID * sizeof(float));
    cudaMemsetAsync(p_pm1, 0xFF, NGRAPH * HID * sizeof(float));
    cudaMemsetAsync(p_pm2, 0xFF, NGRAPH * HID * sizeof(float));

    k_padx<<<(N_NODES * F_PAD + 255) / 256, 256>>>(x);
    k_ew<<<(N_EDGES + 255) / 256, 256>>>(edge_a, bond_w, bond_b);

    k_scatter1<<<N_EDGES / 16, 256>>>(ei);   // E*16 threads, exact grid
    k_dense_pool<50, F_PAD, F_INF, true, true>
        <<<(N_NODES + MTILE - 1) / MTILE, 256, SMEM1>>>(
        p_agg1, x, c1rw, c1rb, c1ow, batch, p_h1, p_pm1, p_ps1);

    k_scatter2<<<N_EDGES / 16, 256>>>(ei);   // E*16 threads, exact grid
    k_dense_pool<64, HID, HID, false, false>
        <<<(N_NODES + MTILE - 1) / MTILE, 256, SMEM2>>>(
        p_agg2, p_h1, c2rw, c2rb, c2ow, batch, nullptr, p_pm2, p_ps2);

    k_head<<<NGRAPH, 64>>>(batch, l1w, l1b, l2w, l2b, out);
}

// round 15
// speedup vs baseline: 1.0655x; 1.0655x over previous
#include <cuda_runtime.h>
#include <cstdint>

#define N_NODES 100000
#define N_EDGES 1600000
#define F_INF   50
#define F_PAD   52            // padded row stride for float4 alignment
#define HID     64
#define NGRAPH  512
#define NCLS    10
#define BONDD   10

#define MTILE   128           // nodes per dense block
#define KC      16            // k-chunk staged in smem (double-buffered)
#define SA_STR  132           // sA row stride (floats), mult of 4 for LDS.128
#define SW_STR  68            // sW row stride (floats), mult of 4

// ---------------- scratch (static __device__ — no allocations) ----------------
__device__ __align__(16) float d_ew[N_EDGES];
__device__ __align__(16) float d_x52[N_NODES * F_PAD];
__device__ __align__(16) float d_agg1[N_NODES * F_PAD];
__device__ __align__(16) float d_h1[N_NODES * HID];       // stores relu(h1)
__device__ __align__(16) float d_agg2[N_NODES * HID];
__device__ __align__(16) float d_psum1[NGRAPH * HID];
__device__ __align__(16) float d_pmax1[NGRAPH * HID];
__device__ __align__(16) float d_psum2[NGRAPH * HID];
__device__ __align__(16) float d_pmax2[NGRAPH * HID];

// ---------------- helpers ----------------
__device__ __forceinline__ void redAdd4(float* a, float x, float y, float z, float w) {
    asm volatile("red.global.add.v4.f32 [%0], {%1,%2,%3,%4};"
                 :: "l"(a), "f"(x), "f"(y), "f"(z), "f"(w) : "memory");
}
__device__ __forceinline__ void atomicMaxF(float* addr, float v) {
    if (v >= 0.0f) atomicMax((int*)addr, __float_as_int(v));
    else           atomicMin((unsigned int*)addr, __float_as_uint(v));
}
// packed fp32x2 (full fp32 precision, 2x issue density)
__device__ __forceinline__ uint64_t pack2(float lo, float hi) {
    uint64_t r; asm("mov.b64 %0, {%1, %2};" : "=l"(r) : "f"(lo), "f"(hi)); return r;
}
__device__ __forceinline__ void unpack2(float& lo, float& hi, uint64_t v) {
    asm("mov.b64 {%0, %1}, %2;" : "=f"(lo), "=f"(hi) : "l"(v));
}
__device__ __forceinline__ void fma2(uint64_t& d, uint64_t a, uint64_t b) {
    asm("fma.rn.f32x2 %0, %1, %2, %0;" : "+l"(d) : "l"(a), "l"(b));
}

// ---------------- small kernels ----------------
__global__ void k_padx(const float* __restrict__ x) {
    int idx = blockIdx.x * blockDim.x + threadIdx.x;
    if (idx >= N_NODES * F_PAD) return;
    int n = idx / F_PAD;
    int f = idx - n * F_PAD;
    d_x52[idx] = (f < F_INF) ? x[n * F_INF + f] : 0.0f;
}

__global__ void k_ew(const float* __restrict__ edge_a,
                     const float* __restrict__ bond_w,
                     const float* __restrict__ bond_b) {
    int e = blockIdx.x * blockDim.x + threadIdx.x;
    if (e >= N_EDGES) return;
    const float2* a2 = (const float2*)(edge_a + e * BONDD);
    float acc = bond_b[0];
#pragma unroll
    for (int i = 0; i < 5; i++) {
        float2 v = a2[i];
        acc += v.x * bond_w[2 * i] + v.y * bond_w[2 * i + 1];
    }
    d_ew[e] = acc;
}

// conv1 scatter: 13 float4 per edge (52 padded floats) — R11 proven form
__global__ __launch_bounds__(256) void k_scatter1(const int* __restrict__ ei) {
    int idx = blockIdx.x * blockDim.x + threadIdx.x;
    if (idx >= N_EDGES * 13) return;
    int e = idx / 13;
    int q = idx - e * 13;
    int src = ei[e];
    int dst = ei[N_EDGES + e];
    float w = d_ew[e];
    float4 v = ((const float4*)(d_x52 + src * F_PAD))[q];
    redAdd4(d_agg1 + dst * F_PAD + q * 4, v.x * w, v.y * w, v.z * w, v.w * w);
}

// conv2 scatter: msg = h1r[src] * ew (h1 already relu'd), 16 float4 per edge
__global__ __launch_bounds__(256) void k_scatter2(const int* __restrict__ ei) {
    int idx = blockIdx.x * blockDim.x + threadIdx.x;
    if (idx >= N_EDGES * 16) return;
    int e = idx >> 4;
    int q = idx & 15;
    int src = ei[e];
    int dst = ei[N_EDGES + e];
    float w = d_ew[e];
    float4 v = ((const float4*)(d_h1 + src * HID))[q];
    redAdd4(d_agg2 + dst * HID + q * 4, v.x * w, v.y * w, v.z * w, v.w * w);
}

// Dense GEMM + fused pooling: h = [agg|xin] @ [rel|root]^T + b.
// 128 nodes x 64 cols per block, 256 threads, 8x4 reg tile.
// Mainloop uses packed fma.rn.f32x2: accumulators pair adjacent NODES, so
// a-pairs come free from LDS.128 float4s; w is duplicated per column.
// A staged in KC=16 chunks, double-buffered via register staging. 4 CTAs/SM.
template <int F, int ASTRIDE, int XSTRIDE, bool STORE_H, bool RELU_STORE>
__global__ __launch_bounds__(256, 4) void k_dense_pool(
    const float* __restrict__ aggp, const float* __restrict__ xin,
    const float* __restrict__ rel_w, const float* __restrict__ rel_b,
    const float* __restrict__ root_w, const int* __restrict__ batch,
    float* __restrict__ h_out, float* __restrict__ pmax, float* __restrict__ psum) {
    constexpr int K  = 2 * F;
    constexpr int NC = (K + KC - 1) / KC;
    constexpr int KP = NC * KC;
    extern __shared__ float smem[];
    float* sW = smem;                  // [KP][SW_STR]
    float* sA = smem + KP * SW_STR;    // [2][KC][SA_STR]

    int tid = threadIdx.x;
    int node0 = blockIdx.x * MTILE;

    for (int idx = tid; idx < 64 * KP; idx += 256) {
        int j = idx / KP;
        int kg = idx - j * KP;
        float w = 0.0f;
        if (kg < F)      w = rel_w[j * F + kg];
        else if (kg < K) w = root_w[j * F + (kg - F)];
        sW[kg * SW_STR + j] = w;
    }

    auto ldA = [&](int c, float r[8]) {
#pragma unroll
        for (int i = 0; i < 8; i++) {
            int idx = tid + i * 256;
            int m  = idx >> 4;
            int kk = idx & 15;
            int kg = c * KC + kk;
            int node = node0 + m;
            float v = 0.0f;
            if (node < N_NODES) {
                if (kg < F)      v = aggp[node * ASTRIDE + kg];
                else if (kg < K) v = xin[node * XSTRIDE + (kg - F)];
            }
            r[i] = v;
        }
    };
    auto stA = [&](int c, const float r[8]) {
        float* buf = sA + (c & 1) * KC * SA_STR;
#pragma unroll
        for (int i = 0; i < 8; i++) {
            int idx = tid + i * 256;
            int m  = idx >> 4;
            int kk = idx & 15;
            buf[kk * SA_STR + m] = r[i];
        }
    };

    { float r[8]; ldA(0, r); stA(0, r); }
    __syncthreads();

    int tx = tid & 15;   // cols tx*4..+3
    int ty = tid >> 4;   // nodes ty*8..+7 (4 node-pairs)
    uint64_t acc2[4][4] = {};   // [node-pair][col] packed fp32x2

    for (int c = 0; c < NC; c++) {
        float r[8];
        if (c + 1 < NC) ldA(c + 1, r);
        const float* buf = sA + (c & 1) * KC * SA_STR;
        const float4* pA0 = (const float4*)(buf + ty * 8);
        const float4* pA1 = (const float4*)(buf + ty * 8 + 4);
        const float4* pW  = (const float4*)(sW + c * KC * SW_STR + tx * 4);
#pragma unroll
        for (int kk = 0; kk < KC; kk++) {
            float4 a0 = pA0[kk * (SA_STR / 4)];
            float4 a1 = pA1[kk * (SA_STR / 4)];
            float4 w  = pW [kk * (SW_STR / 4)];
            uint64_t p0 = pack2(a0.x, a0.y);
            uint64_t p1 = pack2(a0.z, a0.w);
            uint64_t p2 = pack2(a1.x, a1.y);
            uint64_t p3 = pack2(a1.z, a1.w);
            uint64_t w0 = pack2(w.x, w.x);
            uint64_t w1 = pack2(w.y, w.y);
            uint64_t w2 = pack2(w.z, w.z);
            uint64_t w3 = pack2(w.w, w.w);
            fma2(acc2[0][0], p0, w0); fma2(acc2[0][1], p0, w1);
            fma2(acc2[0][2], p0, w2); fma2(acc2[0][3], p0, w3);
            fma2(acc2[1][0], p1, w0); fma2(acc2[1][1], p1, w1);
            fma2(acc2[1][2], p1, w2); fma2(acc2[1][3], p1, w3);
            fma2(acc2[2][0], p2, w0); fma2(acc2[2][1], p2, w1);
            fma2(acc2[2][2], p2, w2); fma2(acc2[2][3], p2, w3);
            fma2(acc2[3][0], p3, w0); fma2(acc2[3][1], p3, w1);
            fma2(acc2[3][2], p3, w2); fma2(acc2[3][3], p3, w3);
        }
        if (c + 1 < NC) stA(c + 1, r);
        __syncthreads();
    }

    float bias[4] = { rel_b[tx * 4 + 0], rel_b[tx * 4 + 1],
                      rel_b[tx * 4 + 2], rel_b[tx * 4 + 3] };

    float* sT = smem;                        // [MTILE][65]
    int*   sB = (int*)(smem + MTILE * 65);   // [MTILE]
    for (int m = tid; m < MTILE; m += 256)
        sB[m] = (node0 + m < N_NODES) ? batch[node0 + m] : -1;

#pragma unroll
    for (int r = 0; r < 4; r++) {
        float* rowLo = sT + (ty * 8 + 2 * r)     * 65 + tx * 4;
        float* rowHi = sT + (ty * 8 + 2 * r + 1) * 65 + tx * 4;
#pragma unroll
        for (int j = 0; j < 4; j++) {
            float lo, hi;
            unpack2(lo, hi, acc2[r][j]);
            rowLo[j] = lo + bias[j];
            rowHi[j] = hi + bias[j];
        }
    }
    __syncthreads();

    if (STORE_H) {
        for (int idx = tid; idx < MTILE * 16; idx += 256) {
            int m = idx >> 4;
            int cg = idx & 15;
            int node = node0 + m;
            if (node < N_NODES) {
                float* row = sT + m * 65 + cg * 4;
                float4 o = make_float4(row[0], row[1], row[2], row[3]);
                if (RELU_STORE) {
                    o.x = fmaxf(o.x, 0.0f); o.y = fmaxf(o.y, 0.0f);
                    o.z = fmaxf(o.z, 0.0f); o.w = fmaxf(o.w, 0.0f);
                }
                *(float4*)(h_out + node * HID + cg * 4) = o;
            }
        }
    }

    {
        int col = tid & 63;
        int sub = tid >> 6;
        int base = sub * 32;
        int g_cur = sB[base];
        float sm = 0.0f;
        float mx = __int_as_float(0xff800000);
#pragma unroll 4
        for (int k = 0; k < 32; k++) {
            int g = sB[base + k];
            if (g < 0) break;
            if (g != g_cur) {
                atomicAdd(&psum[g_cur * HID + col], sm);
                atomicMaxF(&pmax[g_cur * HID + col], mx);
                sm = 0.0f; mx = __int_as_float(0xff800000);
                g_cur = g;
            }
            float vv = sT[(base + k) * 65 + col];
            sm += vv;
            mx = fmaxf(mx, vv);
        }
        if (g_cur >= 0) {
            atomicAdd(&psum[g_cur * HID + col], sm);
            atomicMaxF(&pmax[g_cur * HID + col], mx);
        }
    }
}

// head: counts via binary search on sorted batch; 2-layer MLP per graph.
__global__ __launch_bounds__(64) void k_head(
    const int* __restrict__ batch,
    const float* __restrict__ l1w, const float* __restrict__ l1b,
    const float* __restrict__ l2w, const float* __restrict__ l2b,
    float* __restrict__ out) {
    __shared__ float sg[2 * HID];
    __shared__ float sh[HID];
    __shared__ float scnt;
    int g = blockIdx.x;
    int j = threadIdx.x;
    if (j == 0) {
        int lo = 0, hi = N_NODES;
        while (lo < hi) { int m = (lo + hi) >> 1; if (batch[m] < g) lo = m + 1; else hi = m; }
        int lo2 = lo, hi2 = N_NODES;
        while (lo2 < hi2) { int m = (lo2 + hi2) >> 1; if (batch[m] < g + 1) lo2 = m + 1; else hi2 = m; }
        scnt = (float)(lo2 - lo);
    }
    __syncthreads();
    float inv = 1.0f / fmaxf(scnt, 1.0f);
    sg[j]       = d_pmax1[g * HID + j] + d_pmax2[g * HID + j];
    sg[HID + j] = (d_psum1[g * HID + j] + d_psum2[g * HID + j]) * inv;
    __syncthreads();
    float acc = l1b[j];
#pragma unroll 8
    for (int k = 0; k < 2 * HID; k++) acc += l1w[j * 2 * HID + k] * sg[k];
    sh[j] = fmaxf(acc, 0.0f);
    __syncthreads();
    if (j < NCLS) {
        float o = l2b[j];
#pragma unroll 8
        for (int k = 0; k < HID; k++) o += l2w[j * HID + k] * sh[k];
        out[g * NCLS + j] = o;
    }
}

// ---------------- launch ----------------
extern "C" void kernel_launch(void* const* d_in, const int* in_sizes, int n_in,
                              void* d_out, int out_size) {
    (void)in_sizes; (void)n_in; (void)out_size;
    const float* x      = (const float*)d_in[0];
    const float* edge_a = (const float*)d_in[1];
    const float* bond_w = (const float*)d_in[2];
    const float* bond_b = (const float*)d_in[3];
    const float* c1rw   = (const float*)d_in[4];
    const float* c1rb   = (const float*)d_in[5];
    const float* c1ow   = (const float*)d_in[6];
    const float* c2rw   = (const float*)d_in[7];
    const float* c2rb   = (const float*)d_in[8];
    const float* c2ow   = (const float*)d_in[9];
    const float* l1w    = (const float*)d_in[10];
    const float* l1b    = (const float*)d_in[11];
    const float* l2w    = (const float*)d_in[12];
    const float* l2b    = (const float*)d_in[13];
    const int*   ei     = (const int*)d_in[14];
    const int*   batch  = (const int*)d_in[15];
    float* out = (float*)d_out;

    float *p_agg1, *p_agg2, *p_h1, *p_ps1, *p_pm1, *p_ps2, *p_pm2;
    cudaGetSymbolAddress((void**)&p_agg1, d_agg1);
    cudaGetSymbolAddress((void**)&p_agg2, d_agg2);
    cudaGetSymbolAddress((void**)&p_h1,   d_h1);
    cudaGetSymbolAddress((void**)&p_ps1,  d_psum1);
    cudaGetSymbolAddress((void**)&p_pm1,  d_pmax1);
    cudaGetSymbolAddress((void**)&p_ps2,  d_psum2);
    cudaGetSymbolAddress((void**)&p_pm2,  d_pmax2);

    const int KP1 = ((100 + KC - 1) / KC) * KC;  // 112
    const int KP2 = ((128 + KC - 1) / KC) * KC;  // 128
    const int SMEM1 = (KP1 * SW_STR + 2 * KC * SA_STR) * (int)sizeof(float);  // ~47.4 KB
    const int SMEM2 = (KP2 * SW_STR + 2 * KC * SA_STR) * (int)sizeof(float);  // ~51.7 KB
    cudaFuncSetAttribute((const void*)k_dense_pool<50, F_PAD, F_INF, true, true>,
                         cudaFuncAttributeMaxDynamicSharedMemorySize, SMEM1);
    cudaFuncSetAttribute((const void*)k_dense_pool<64, HID, HID, false, false>,
                         cudaFuncAttributeMaxDynamicSharedMemorySize, SMEM2);

    cudaMemsetAsync(p_agg1, 0, N_NODES * F_PAD * sizeof(float));
    cudaMemsetAsync(p_agg2, 0, N_NODES * HID * sizeof(float));
    cudaMemsetAsync(p_ps1, 0, NGRAPH * HID * sizeof(float));
    cudaMemsetAsync(p_ps2, 0, NGRAPH * HID * sizeof(float));
    cudaMemsetAsync(p_pm1, 0xFF, NGRAPH * HID * sizeof(float));
    cudaMemsetAsync(p_pm2, 0xFF, NGRAPH * HID * sizeof(float));

    k_padx<<<(N_NODES * F_PAD + 255) / 256, 256>>>(x);
    k_ew<<<(N_EDGES + 255) / 256, 256>>>(edge_a, bond_w, bond_b);

    k_scatter1<<<(N_EDGES * 13 + 255) / 256, 256>>>(ei);
    k_dense_pool<50, F_PAD, F_INF, true, true>
        <<<(N_NODES + MTILE - 1) / MTILE, 256, SMEM1>>>(
        p_agg1, x, c1rw, c1rb, c1ow, batch, p_h1, p_pm1, p_ps1);

    k_scatter2<<<(N_EDGES * 16 + 255) / 256, 256>>>(ei);
    k_dense_pool<64, HID, HID, false, false>
        <<<(N_NODES + MTILE - 1) / MTILE, 256, SMEM2>>>(
        p_agg2, p_h1, c2rw, c2rb, c2ow, batch, nullptr, p_pm2, p_ps2);

    k_head<<<NGRAPH, 64>>>(batch, l1w, l1b, l2w, l2b, out);
}